// round 12
// baseline (speedup 1.0000x reference)
#include <cuda_runtime.h>
#include <cuda_fp16.h>
#include <cstdint>

#define HID 1024
#define SEQ 512
#define BATCH 2
#define NH 16
#define HD 64
#define ROWS (BATCH*SEQ)
#define NKEY (SEQ*NH)
#define NT 128
#define NPART 2
#define NTP (NT/NPART)          // 64 key-tiles per part

// Scratch (device globals)
__device__ __half g_qh[ROWS*HID];            // Q pre-scaled by 0.125*log2(e)
__device__ __half g_kh[ROWS*HID];            // K, [b][j][d]
__device__ __half g_vt[BATCH*HD*NKEY];       // V^T, [b][dd][j]
__device__ __half g_att[ROWS*HID];           // scrambled attention output
__device__ __half g_xh[ROWS*HID];            // x in fp16
__device__ __half g_wh[4*HID*HID];           // W^T in fp16: [z][n][k]
__device__ float  g_po[NPART*ROWS*HID];      // partial O, scrambled layout, fp32
__device__ float  g_pl[NPART*BATCH*NH*SEQ];  // partial lsum [p][b][h][s]

#define QSCALE 0.18033688f                   // 0.125 * log2(e)
#define ONES2  0x3C003C00u                   // half2(1.0, 1.0)

// ---------------------------------------------------------------------------
__device__ __forceinline__ uint32_t h2bits(__half2 h){ return *(uint32_t*)&h; }
__device__ __forceinline__ void mma16(float* c, const uint32_t* a, uint32_t b0, uint32_t b1){
    asm volatile("mma.sync.aligned.m16n8k16.row.col.f32.f16.f16.f32 "
                 "{%0,%1,%2,%3},{%4,%5,%6,%7},{%8,%9},{%0,%1,%2,%3};"
                 : "+f"(c[0]),"+f"(c[1]),"+f"(c[2]),"+f"(c[3])
                 : "r"(a[0]),"r"(a[1]),"r"(a[2]),"r"(a[3]),"r"(b0),"r"(b1));
}
__device__ __forceinline__ void ldsm4(uint32_t* r, uint32_t addr){
    asm volatile("ldmatrix.sync.aligned.m8n8.x4.shared.b16 {%0,%1,%2,%3}, [%4];"
                 : "=r"(r[0]),"=r"(r[1]),"=r"(r[2]),"=r"(r[3]) : "r"(addr));
}
__device__ __forceinline__ float ex2(float x){
    float r; asm("ex2.approx.f32 %0, %1;" : "=f"(r) : "f"(x)); return r;
}
__device__ __forceinline__ void cp16(uint32_t dst, const void* src){
    asm volatile("cp.async.cg.shared.global [%0], [%1], 16;" :: "r"(dst), "l"(src));
}
__device__ __forceinline__ uint32_t smem_u32(const void* p){
    uint32_t a;
    asm("{ .reg .u64 t; cvta.to.shared.u64 t, %1; cvt.u32.u64 %0, t; }" : "=r"(a) : "l"(p));
    return a;
}
#define CP_COMMIT() asm volatile("cp.async.commit_group;")
#define CP_WAIT0()  asm volatile("cp.async.wait_group 0;")

// ---------------------------------------------------------------------------
// x -> fp16. grid 1024, 256 thr.
// ---------------------------------------------------------------------------
__global__ __launch_bounds__(256)
void round_x_kernel(const float* __restrict__ x)
{
    size_t i = ((size_t)blockIdx.x*256 + threadIdx.x)*4;
    float4 v = *(const float4*)(x + i);
    __half2 lo = __floats2half2_rn(v.x, v.y);
    __half2 hi = __floats2half2_rn(v.z, v.w);
    *(uint2*)(g_xh + i) = make_uint2(h2bits(lo), h2bits(hi));
}

// ---------------------------------------------------------------------------
// W[k][n] -> W^T fp16 [z][n][k]. grid (16,16,4), 256 thr.
// ---------------------------------------------------------------------------
__global__ __launch_bounds__(256)
void transw_kernel(const float* __restrict__ Wq, const float* __restrict__ Wk,
                   const float* __restrict__ Wv, const float* __restrict__ Wo)
{
    __shared__ float ts[64][65];
    const int z = blockIdx.z;
    const float* W = (z==0)?Wq:(z==1)?Wk:(z==2)?Wv:Wo;
    const int k0 = blockIdx.x*64, n0 = blockIdx.y*64;
    const int tid = threadIdx.x;

    #pragma unroll
    for (int t = 0; t < 4; t++) {
        int idx = tid + 256*t;
        int r = idx >> 4, c4 = (idx & 15) << 2;
        float4 v = *(const float4*)(W + (size_t)(k0+r)*HID + n0 + c4);
        ts[r][c4] = v.x; ts[r][c4+1] = v.y; ts[r][c4+2] = v.z; ts[r][c4+3] = v.w;
    }
    __syncthreads();
    #pragma unroll
    for (int t = 0; t < 4; t++) {
        int idx = tid + 256*t;
        int r = idx >> 4, c4 = (idx & 15) << 2;
        __half2 lo = __floats2half2_rn(ts[c4][r],   ts[c4+1][r]);
        __half2 hi = __floats2half2_rn(ts[c4+2][r], ts[c4+3][r]);
        *(uint2*)(g_wh + (size_t)z*HID*HID + (size_t)(n0+r)*HID + k0 + c4) =
            make_uint2(h2bits(lo), h2bits(hi));
    }
}

// ---------------------------------------------------------------------------
// fp16 mma GEMM (unchanged).
// ---------------------------------------------------------------------------
#define AST 40
#define BST 40
#define ASZ (64*AST)
#define BSZ (128*BST)
#define GEMM_SMEM ((2*ASZ + 2*BSZ)*2)

__device__ __forceinline__ void gemm_fp16_body(const __half* __restrict__ A,
                                               const __half* __restrict__ Wt,
                                               const float* __restrict__ bias,
                                               int mode, float* __restrict__ outf)
{
    extern __shared__ __align__(16) char smc[];
    __half* sh = (__half*)smc;
    const uint32_t sb = smem_u32(sh);
    __half* Asb[2] = { sh, sh + ASZ };
    __half* Bsb[2] = { sh + 2*ASZ, sh + 2*ASZ + BSZ };
    const uint32_t au[2] = { sb, sb + ASZ*2u };
    const uint32_t bu[2] = { sb + 2u*ASZ*2u, sb + (2u*ASZ + BSZ)*2u };

    const int tid = threadIdx.x;
    const int w = tid >> 5, lane = tid & 31;
    const int g = lane >> 2, q = lane & 3;
    const int wr = w >> 2, wc = w & 3;
    const int m0 = blockIdx.y*64, n0 = blockIdx.x*128;

    float cacc[2][4][4];
    #pragma unroll
    for (int mf = 0; mf < 2; mf++)
        #pragma unroll
        for (int nf = 0; nf < 4; nf++)
            #pragma unroll
            for (int j = 0; j < 4; j++) cacc[mf][nf][j] = 0.f;

    {
        int ar = tid >> 2, ac = (tid & 3) << 3;
        cp16(au[0] + (ar*AST + ac)*2u, A + (size_t)(m0+ar)*HID + ac);
        #pragma unroll
        for (int t = 0; t < 2; t++) {
            int c = tid + 256*t;
            int br = c >> 2, bc = (c & 3) << 3;
            cp16(bu[0] + (br*BST + bc)*2u, Wt + (size_t)(n0+br)*HID + bc);
        }
        CP_COMMIT();
    }

    for (int kt = 0; kt < HID/32; kt++) {
        CP_WAIT0();
        __syncthreads();
        if (kt + 1 < HID/32) {
            int nb = (kt+1) & 1, k0 = (kt+1)*32;
            int ar = tid >> 2, ac = (tid & 3) << 3;
            cp16(au[nb] + (ar*AST + ac)*2u, A + (size_t)(m0+ar)*HID + k0 + ac);
            #pragma unroll
            for (int t = 0; t < 2; t++) {
                int c = tid + 256*t;
                int br = c >> 2, bc = (c & 3) << 3;
                cp16(bu[nb] + (br*BST + bc)*2u, Wt + (size_t)(n0+br)*HID + k0 + bc);
            }
            CP_COMMIT();
        }
        const __half* Ab = Asb[kt & 1];
        const __half* Bb = Bsb[kt & 1];

        #pragma unroll
        for (int kk = 0; kk < 2; kk++) {
            uint32_t af[2][4], bf[4][2];
            #pragma unroll
            for (int mf = 0; mf < 2; mf++) {
                int r0 = 32*wr + 16*mf;
                af[mf][0] = h2bits(*(const __half2*)(Ab + (r0+g  )*AST + 16*kk + 2*q));
                af[mf][1] = h2bits(*(const __half2*)(Ab + (r0+8+g)*AST + 16*kk + 2*q));
                af[mf][2] = h2bits(*(const __half2*)(Ab + (r0+g  )*AST + 16*kk + 8 + 2*q));
                af[mf][3] = h2bits(*(const __half2*)(Ab + (r0+8+g)*AST + 16*kk + 8 + 2*q));
            }
            #pragma unroll
            for (int nf = 0; nf < 4; nf++) {
                int col = 32*wc + 8*nf + g;
                bf[nf][0] = h2bits(*(const __half2*)(Bb + col*BST + 16*kk + 2*q));
                bf[nf][1] = h2bits(*(const __half2*)(Bb + col*BST + 16*kk + 8 + 2*q));
            }
            #pragma unroll
            for (int mf = 0; mf < 2; mf++)
                #pragma unroll
                for (int nf = 0; nf < 4; nf++)
                    mma16(cacc[mf][nf], af[mf], bf[nf][0], bf[nf][1]);
        }
    }

    #pragma unroll
    for (int mf = 0; mf < 2; mf++) {
        #pragma unroll
        for (int rr = 0; rr < 2; rr++) {
            int row = m0 + 32*wr + 16*mf + 8*rr + g;
            #pragma unroll
            for (int nf = 0; nf < 4; nf++) {
                int col = n0 + 32*wc + 8*nf + 2*q;
                float o0 = cacc[mf][nf][rr*2]   + __ldg(bias + col);
                float o1 = cacc[mf][nf][rr*2+1] + __ldg(bias + col + 1);
                if (mode == 0) {
                    __half2 h = __floats2half2_rn(o0*QSCALE, o1*QSCALE);
                    *(uint32_t*)(g_qh + (size_t)row*HID + col) = h2bits(h);
                } else if (mode == 1) {
                    __half2 h = __floats2half2_rn(o0, o1);
                    *(uint32_t*)(g_kh + (size_t)row*HID + col) = h2bits(h);
                } else if (mode == 2) {
                    int hh = col >> 6, dd = col & 63;
                    int s = row & 511, bb = row >> 9;
                    __half* dst = g_vt + (size_t)bb*HD*NKEY + s*16 + hh;
                    dst[(size_t)dd*NKEY]     = __float2half_rn(o0);
                    dst[(size_t)(dd+1)*NKEY] = __float2half_rn(o1);
                } else {
                    *(float2*)(outf + (size_t)row*HID + col) = make_float2(o0, o1);
                }
            }
        }
    }
}

__global__ __launch_bounds__(256)
void qkv_kernel(const float* __restrict__ bq, const float* __restrict__ bk,
                const float* __restrict__ bv)
{
    int z = blockIdx.z;
    const float* bias = (z == 0) ? bq : (z == 1) ? bk : bv;
    gemm_fp16_body(g_xh, g_wh + (size_t)z*HID*HID, bias, z, nullptr);
}

__global__ __launch_bounds__(256)
void oproj_kernel(const float* __restrict__ bo, float* __restrict__ out)
{
    gemm_fp16_body(g_att, g_wh + (size_t)3*HID*HID, bo, 3, out);
}

// ---------------------------------------------------------------------------
// fp16 mma flash attention, key-split 2 ways, M-blocked warps.
// 512 CTAs = part(2) x B(2) x H(16) x Qtiles(8x64rows), 256 thr = 8 warps.
// Warp: rg=w&1 (32 rows = 2 m-frags), kh=w>>1 (16-key quarter).
// Per warp-tile: 4 K-ldsm4 + 4 V-ldsm4 (halved smem traffic), Q in registers.
// ---------------------------------------------------------------------------
#define KSTH 72
#define KBUF (64*KSTH)
#define OSM_ST 66
#define ATTN_SMEM (4*KBUF*2 + 1280)

__global__ __launch_bounds__(256, 2)
void attn_kernel()
{
    extern __shared__ __align__(16) char smc[];
    __half* sh = (__half*)smc;
    const uint32_t sb = smem_u32(sh);
    const uint32_t ku[2] = { sb, sb + KBUF*2u };
    const uint32_t vu[2] = { sb + 2u*KBUF*2u, sb + 3u*KBUF*2u };
    float* lsumS = (float*)(smc + 4*KBUF*2);   // [4][64]
    float* Osm   = (float*)smc;                // epilogue reuse of K/V region

    const int tid = threadIdx.x;
    const int w = tid >> 5, lane = tid & 31;
    const int g = lane >> 2, q = lane & 3;
    const int lr = lane & 7, lm = lane >> 3;
    const int rg = w & 1, kh = w >> 1;          // rg: 32-row group; kh: 16-key quarter
    const int bx = blockIdx.x;
    const int p  = bx >> 8;
    const int b  = (bx >> 7) & 1;
    const int h  = (bx >> 3) & 15;
    const int s0 = (bx & 7) << 6;

    const __half* kb0 = g_kh + (size_t)b*SEQ*HID;     // [8192][64]
    const __half* vt0 = g_vt + (size_t)b*HD*NKEY;     // [64][8192]
    const int jt0 = p*NTP;

    // prefetch coords: 512 16B-chunks per tile (8 per 64-half row), 2 per thread
    const int pr0 = tid >> 3, pc0 = (tid & 7) << 3;   // rows 0..31
    const int pr1 = pr0 + 32, pc1 = pc0;              // rows 32..63

    {
        const __half* kp = kb0 + (size_t)jt0*64*HD;
        const __half* vp = vt0 + jt0*64;
        cp16(ku[0] + (pr0*KSTH + pc0)*2u, kp + (size_t)pr0*HD + pc0);
        cp16(ku[0] + (pr1*KSTH + pc1)*2u, kp + (size_t)pr1*HD + pc1);
        cp16(vu[0] + (pr0*KSTH + pc0)*2u, vp + (size_t)pr0*NKEY + pc0);
        cp16(vu[0] + (pr1*KSTH + pc1)*2u, vp + (size_t)pr1*NKEY + pc1);
        CP_COMMIT();
    }

    // Q fragments from gmem (pre-scaled fp16): 2 m-frags x 4 kt
    uint32_t qf[2][4][4];
    {
        const __half* qb = g_qh + (size_t)(b*SEQ + s0)*HID + h*HD;
        #pragma unroll
        for (int m = 0; m < 2; m++) {
            const __half* q0 = qb + (size_t)(32*rg + 16*m + g)*HID;
            const __half* q1 = q0 + (size_t)8*HID;
            #pragma unroll
            for (int kt = 0; kt < 4; kt++) {
                qf[m][kt][0] = h2bits(*(const __half2*)(q0 + 16*kt + 2*q));
                qf[m][kt][1] = h2bits(*(const __half2*)(q1 + 16*kt + 2*q));
                qf[m][kt][2] = h2bits(*(const __half2*)(q0 + 16*kt + 8 + 2*q));
                qf[m][kt][3] = h2bits(*(const __half2*)(q1 + 16*kt + 8 + 2*q));
            }
        }
    }

    // per-lane LDSM base offsets (bytes); 16-key quarter maps (validated in R9)
    const uint32_t koff = (uint32_t)(((16*kh + lr)*KSTH + 16*(lm >> 1) + 8*(lm & 1))*2);
    const uint32_t voff = (uint32_t)(((8*(lm >> 1) + lr)*KSTH + 16*kh + 8*(lm & 1))*2);

    float Oacc[2][8][4];
    #pragma unroll
    for (int m = 0; m < 2; m++)
        #pragma unroll
        for (int nt = 0; nt < 8; nt++)
            #pragma unroll
            for (int j = 0; j < 4; j++) Oacc[m][nt][j] = 0.f;
    float lacc[2][4] = {{0.f,0.f,0.f,0.f},{0.f,0.f,0.f,0.f}};

    for (int t = 0; t < NTP; t++) {
        CP_WAIT0();
        __syncthreads();
        if (t + 1 < NTP) {
            int nb = (t+1) & 1;
            const __half* kp = kb0 + (size_t)(jt0+t+1)*64*HD;
            const __half* vp = vt0 + (jt0+t+1)*64;
            cp16(ku[nb] + (pr0*KSTH + pc0)*2u, kp + (size_t)pr0*HD + pc0);
            cp16(ku[nb] + (pr1*KSTH + pc1)*2u, kp + (size_t)pr1*HD + pc1);
            cp16(vu[nb] + (pr0*KSTH + pc0)*2u, vp + (size_t)pr0*NKEY + pc0);
            cp16(vu[nb] + (pr1*KSTH + pc1)*2u, vp + (size_t)pr1*NKEY + pc1);
            CP_COMMIT();
        }
        const uint32_t kcur = ku[t & 1] + koff;
        const uint32_t vcur = vu[t & 1] + voff;

        // ---- S = Q @ K^T : 32 rows x 16 keys (2 chunks of 8 keys) ----
        float pch[2][2][4];
        #pragma unroll
        for (int m = 0; m < 2; m++)
            #pragma unroll
            for (int c = 0; c < 2; c++)
                #pragma unroll
                for (int j = 0; j < 4; j++) pch[m][c][j] = 0.f;

        #pragma unroll
        for (int c = 0; c < 2; c++) {
            uint32_t kf[8];
            ldsm4(kf,     kcur + (uint32_t)(c*8*KSTH*2));
            ldsm4(kf + 4, kcur + (uint32_t)(c*8*KSTH*2 + 64));
            #pragma unroll
            for (int kt = 0; kt < 4; kt++) {
                mma16(pch[0][c], qf[0][kt], kf[2*kt], kf[2*kt+1]);
                mma16(pch[1][c], qf[1][kt], kf[2*kt], kf[2*kt+1]);
            }
        }

        // ---- P = ex2(S): accumulators map onto PV A-fragments (16-key k) ----
        uint32_t pa[2][4];
        #pragma unroll
        for (int m = 0; m < 2; m++) {
            pa[m][0] = h2bits(__floats2half2_rn(ex2(pch[m][0][0]), ex2(pch[m][0][1])));
            pa[m][1] = h2bits(__floats2half2_rn(ex2(pch[m][0][2]), ex2(pch[m][0][3])));
            pa[m][2] = h2bits(__floats2half2_rn(ex2(pch[m][1][0]), ex2(pch[m][1][1])));
            pa[m][3] = h2bits(__floats2half2_rn(ex2(pch[m][1][2]), ex2(pch[m][1][3])));
        }

        // ---- O += P @ V : V fragments loaded ONCE, reused by both m ----
        #pragma unroll
        for (int np = 0; np < 4; np++) {
            uint32_t vf[4];
            ldsm4(vf, vcur + (uint32_t)(np*16*KSTH*2));
            mma16(Oacc[0][2*np],     pa[0], vf[0], vf[1]);
            mma16(Oacc[0][2*np + 1], pa[0], vf[2], vf[3]);
            mma16(Oacc[1][2*np],     pa[1], vf[0], vf[1]);
            mma16(Oacc[1][2*np + 1], pa[1], vf[2], vf[3]);
        }
        mma16(lacc[0], pa[0], ONES2, ONES2);
        mma16(lacc[1], pa[1], ONES2, ONES2);
    }

    // ---- publish lsum partials; 4-way O combine over key-quarters ----
    __syncthreads();   // all K/V reads done before Osm reuse
    if (q == 0) {
        #pragma unroll
        for (int m = 0; m < 2; m++) {
            int r0 = 32*rg + 16*m + g;
            lsumS[kh*64 + r0]     = lacc[m][0];
            lsumS[kh*64 + r0 + 8] = lacc[m][2];
        }
    }
    if (kh == 0) {
        #pragma unroll
        for (int m = 0; m < 2; m++) {
            int r0 = 32*rg + 16*m + g;
            #pragma unroll
            for (int nt = 0; nt < 8; nt++) {
                *(float2*)(Osm + r0*OSM_ST + 8*nt + 2*q) =
                    make_float2(Oacc[m][nt][0], Oacc[m][nt][1]);
                *(float2*)(Osm + (r0+8)*OSM_ST + 8*nt + 2*q) =
                    make_float2(Oacc[m][nt][2], Oacc[m][nt][3]);
            }
        }
    }
    __syncthreads();
    #pragma unroll
    for (int ph = 1; ph < 3; ph++) {
        if (kh == ph) {
            #pragma unroll
            for (int m = 0; m < 2; m++) {
                int r0 = 32*rg + 16*m + g;
                #pragma unroll
                for (int nt = 0; nt < 8; nt++) {
                    float2* p0 = (float2*)(Osm + r0*OSM_ST + 8*nt + 2*q);
                    float2* p1 = (float2*)(Osm + (r0+8)*OSM_ST + 8*nt + 2*q);
                    p0->x += Oacc[m][nt][0]; p0->y += Oacc[m][nt][1];
                    p1->x += Oacc[m][nt][2]; p1->y += Oacc[m][nt][3];
                }
            }
        }
        __syncthreads();
    }

    if (kh == 3) {
        float* pab = g_po + (size_t)p*ROWS*HID + (size_t)b*SEQ*HID;
        #pragma unroll
        for (int m = 0; m < 2; m++) {
            int r0 = 32*rg + 16*m + g, r1 = r0 + 8;
            float l0 = lsumS[r0] + lsumS[64 + r0] + lsumS[128 + r0] + lsumS[192 + r0];
            float l1 = lsumS[r1] + lsumS[64 + r1] + lsumS[128 + r1] + lsumS[192 + r1];
            int sA = s0 + r0, sB = s0 + r1;
            if (q == 0) {
                g_pl[((p*BATCH + b)*NH + h)*SEQ + sA] = l0;
                g_pl[((p*BATCH + b)*NH + h)*SEQ + sB] = l1;
            }
            #pragma unroll
            for (int nt = 0; nt < 8; nt++) {
                float2 h0 = *(float2*)(Osm + r0*OSM_ST + 8*nt + 2*q);
                float2 h1 = *(float2*)(Osm + r1*OSM_ST + 8*nt + 2*q);
                int e = h*HD + 8*nt + 2*q;
                size_t base = (size_t)(e >> 1)*HID;
                pab[base + sA]       = Oacc[m][nt][0] + h0.x;
                pab[base + SEQ + sA] = Oacc[m][nt][1] + h0.y;
                pab[base + sB]       = Oacc[m][nt][2] + h1.x;
                pab[base + sB + SEQ] = Oacc[m][nt][3] + h1.y;
            }
        }
    }
}

// ---------------------------------------------------------------------------
// Combine: g_att = (po0+po1) / (pl0+pl1), fp16. 1024 blocks x 256 thr, 4/thr.
// ---------------------------------------------------------------------------
__global__ __launch_bounds__(256)
void combine_kernel()
{
    int i = (blockIdx.x*256 + threadIdx.x)*4;     // half index, 4 per thread
    int b = i >> 19;                              // SEQ*HID = 2^19
    int j = i & (SEQ*HID - 1);
    int r = j >> 10, c = j & 1023;
    int h = r >> 5, s = c & 511;

    float4 a0 = *(const float4*)(g_po + i);
    float4 a1 = *(const float4*)(g_po + ROWS*HID + i);
    const float* pl0 = g_pl + (b*NH + h)*SEQ + s;
    const float* pl1 = pl0 + BATCH*NH*SEQ;
    float4 l0 = *(const float4*)pl0;
    float4 l1 = *(const float4*)pl1;

    __half2 o01 = __floats2half2_rn((a0.x + a1.x) / (l0.x + l1.x),
                                    (a0.y + a1.y) / (l0.y + l1.y));
    __half2 o23 = __floats2half2_rn((a0.z + a1.z) / (l0.z + l1.z),
                                    (a0.w + a1.w) / (l0.w + l1.w));
    *(uint2*)(g_att + i) = make_uint2(h2bits(o01), h2bits(o23));
}

// ---------------------------------------------------------------------------
extern "C" void kernel_launch(void* const* d_in, const int* in_sizes, int n_in,
                              void* d_out, int out_size)
{
    const float* x  = (const float*)d_in[0];
    const float* Wq = (const float*)d_in[1];
    const float* bq = (const float*)d_in[2];
    const float* Wk = (const float*)d_in[3];
    const float* bk = (const float*)d_in[4];
    const float* Wv = (const float*)d_in[5];
    const float* bv = (const float*)d_in[6];
    const float* Wo = (const float*)d_in[7];
    const float* bo = (const float*)d_in[8];
    float* out = (float*)d_out;

    cudaFuncSetAttribute(qkv_kernel,
                         cudaFuncAttributeMaxDynamicSharedMemorySize, GEMM_SMEM);
    cudaFuncSetAttribute(oproj_kernel,
                         cudaFuncAttributeMaxDynamicSharedMemorySize, GEMM_SMEM);
    cudaFuncSetAttribute(attn_kernel,
                         cudaFuncAttributeMaxDynamicSharedMemorySize, ATTN_SMEM);

    round_x_kernel<<<1024, 256>>>(x);
    transw_kernel<<<dim3(16,16,4), 256>>>(Wq, Wk, Wv, Wo);

    qkv_kernel<<<dim3(8,16,3), 256, GEMM_SMEM>>>(bq, bk, bv);

    attn_kernel<<<512, 256, ATTN_SMEM>>>();
    combine_kernel<<<ROWS*HID/1024, 256>>>();

    oproj_kernel<<<dim3(8,16), 256, GEMM_SMEM>>>(bo, out);
}

// round 13
// speedup vs baseline: 1.2009x; 1.2009x over previous
#include <cuda_runtime.h>
#include <cuda_fp16.h>
#include <cstdint>

#define HID 1024
#define SEQ 512
#define BATCH 2
#define NH 16
#define HD 64
#define ROWS (BATCH*SEQ)
#define NKEY (SEQ*NH)
#define NT 128
#define NPART 4
#define NTP (NT/NPART)          // 32 key-tiles per part

// Scratch (device globals)
__device__ __half g_qh[ROWS*HID];            // Q pre-scaled by 0.125*log2(e)
__device__ __half g_kh[ROWS*HID];            // K, [b][j][d]
__device__ __half g_vt[BATCH*HD*NKEY];       // V^T, [b][dd][j]
__device__ __half g_att[ROWS*HID];           // scrambled attention output
__device__ __half g_xh[ROWS*HID];            // x in fp16
__device__ __half g_wh[4*HID*HID];           // W^T in fp16: [z][n][k]
__device__ float  g_po[NPART*ROWS*HID];      // partial O, scrambled layout, fp32
__device__ float  g_pl[NPART*BATCH*NH*SEQ];  // partial lsum [p][b][h][s]

#define QSCALE 0.18033688f                   // 0.125 * log2(e)
#define ONES2  0x3C003C00u                   // half2(1.0, 1.0)

// ---------------------------------------------------------------------------
__device__ __forceinline__ uint32_t h2bits(__half2 h){ return *(uint32_t*)&h; }
__device__ __forceinline__ void mma16(float* c, const uint32_t* a, uint32_t b0, uint32_t b1){
    asm volatile("mma.sync.aligned.m16n8k16.row.col.f32.f16.f16.f32 "
                 "{%0,%1,%2,%3},{%4,%5,%6,%7},{%8,%9},{%0,%1,%2,%3};"
                 : "+f"(c[0]),"+f"(c[1]),"+f"(c[2]),"+f"(c[3])
                 : "r"(a[0]),"r"(a[1]),"r"(a[2]),"r"(a[3]),"r"(b0),"r"(b1));
}
__device__ __forceinline__ void ldsm4(uint32_t* r, uint32_t addr){
    asm volatile("ldmatrix.sync.aligned.m8n8.x4.shared.b16 {%0,%1,%2,%3}, [%4];"
                 : "=r"(r[0]),"=r"(r[1]),"=r"(r[2]),"=r"(r[3]) : "r"(addr));
}
__device__ __forceinline__ float ex2(float x){
    float r; asm("ex2.approx.f32 %0, %1;" : "=f"(r) : "f"(x)); return r;
}
__device__ __forceinline__ void cp16(uint32_t dst, const void* src){
    asm volatile("cp.async.cg.shared.global [%0], [%1], 16;" :: "r"(dst), "l"(src));
}
__device__ __forceinline__ uint32_t smem_u32(const void* p){
    uint32_t a;
    asm("{ .reg .u64 t; cvta.to.shared.u64 t, %1; cvt.u32.u64 %0, t; }" : "=r"(a) : "l"(p));
    return a;
}
#define CP_COMMIT() asm volatile("cp.async.commit_group;")
#define CP_WAIT0()  asm volatile("cp.async.wait_group 0;")

// ---------------------------------------------------------------------------
// x -> fp16. grid 1024, 256 thr.
// ---------------------------------------------------------------------------
__global__ __launch_bounds__(256)
void round_x_kernel(const float* __restrict__ x)
{
    size_t i = ((size_t)blockIdx.x*256 + threadIdx.x)*4;
    float4 v = *(const float4*)(x + i);
    __half2 lo = __floats2half2_rn(v.x, v.y);
    __half2 hi = __floats2half2_rn(v.z, v.w);
    *(uint2*)(g_xh + i) = make_uint2(h2bits(lo), h2bits(hi));
}

// ---------------------------------------------------------------------------
// W[k][n] -> W^T fp16 [z][n][k]. grid (16,16,4), 256 thr.
// ---------------------------------------------------------------------------
__global__ __launch_bounds__(256)
void transw_kernel(const float* __restrict__ Wq, const float* __restrict__ Wk,
                   const float* __restrict__ Wv, const float* __restrict__ Wo)
{
    __shared__ float ts[64][65];
    const int z = blockIdx.z;
    const float* W = (z==0)?Wq:(z==1)?Wk:(z==2)?Wv:Wo;
    const int k0 = blockIdx.x*64, n0 = blockIdx.y*64;
    const int tid = threadIdx.x;

    #pragma unroll
    for (int t = 0; t < 4; t++) {
        int idx = tid + 256*t;
        int r = idx >> 4, c4 = (idx & 15) << 2;
        float4 v = *(const float4*)(W + (size_t)(k0+r)*HID + n0 + c4);
        ts[r][c4] = v.x; ts[r][c4+1] = v.y; ts[r][c4+2] = v.z; ts[r][c4+3] = v.w;
    }
    __syncthreads();
    #pragma unroll
    for (int t = 0; t < 4; t++) {
        int idx = tid + 256*t;
        int r = idx >> 4, c4 = (idx & 15) << 2;
        __half2 lo = __floats2half2_rn(ts[c4][r],   ts[c4+1][r]);
        __half2 hi = __floats2half2_rn(ts[c4+2][r], ts[c4+3][r]);
        *(uint2*)(g_wh + (size_t)z*HID*HID + (size_t)(n0+r)*HID + k0 + c4) =
            make_uint2(h2bits(lo), h2bits(hi));
    }
}

// ---------------------------------------------------------------------------
// fp16 mma GEMM (unchanged).
// ---------------------------------------------------------------------------
#define AST 40
#define BST 40
#define ASZ (64*AST)
#define BSZ (128*BST)
#define GEMM_SMEM ((2*ASZ + 2*BSZ)*2)

__device__ __forceinline__ void gemm_fp16_body(const __half* __restrict__ A,
                                               const __half* __restrict__ Wt,
                                               const float* __restrict__ bias,
                                               int mode, float* __restrict__ outf)
{
    extern __shared__ __align__(16) char smc[];
    __half* sh = (__half*)smc;
    const uint32_t sb = smem_u32(sh);
    __half* Asb[2] = { sh, sh + ASZ };
    __half* Bsb[2] = { sh + 2*ASZ, sh + 2*ASZ + BSZ };
    const uint32_t au[2] = { sb, sb + ASZ*2u };
    const uint32_t bu[2] = { sb + 2u*ASZ*2u, sb + (2u*ASZ + BSZ)*2u };

    const int tid = threadIdx.x;
    const int w = tid >> 5, lane = tid & 31;
    const int g = lane >> 2, q = lane & 3;
    const int wr = w >> 2, wc = w & 3;
    const int m0 = blockIdx.y*64, n0 = blockIdx.x*128;

    float cacc[2][4][4];
    #pragma unroll
    for (int mf = 0; mf < 2; mf++)
        #pragma unroll
        for (int nf = 0; nf < 4; nf++)
            #pragma unroll
            for (int j = 0; j < 4; j++) cacc[mf][nf][j] = 0.f;

    {
        int ar = tid >> 2, ac = (tid & 3) << 3;
        cp16(au[0] + (ar*AST + ac)*2u, A + (size_t)(m0+ar)*HID + ac);
        #pragma unroll
        for (int t = 0; t < 2; t++) {
            int c = tid + 256*t;
            int br = c >> 2, bc = (c & 3) << 3;
            cp16(bu[0] + (br*BST + bc)*2u, Wt + (size_t)(n0+br)*HID + bc);
        }
        CP_COMMIT();
    }

    for (int kt = 0; kt < HID/32; kt++) {
        CP_WAIT0();
        __syncthreads();
        if (kt + 1 < HID/32) {
            int nb = (kt+1) & 1, k0 = (kt+1)*32;
            int ar = tid >> 2, ac = (tid & 3) << 3;
            cp16(au[nb] + (ar*AST + ac)*2u, A + (size_t)(m0+ar)*HID + k0 + ac);
            #pragma unroll
            for (int t = 0; t < 2; t++) {
                int c = tid + 256*t;
                int br = c >> 2, bc = (c & 3) << 3;
                cp16(bu[nb] + (br*BST + bc)*2u, Wt + (size_t)(n0+br)*HID + k0 + bc);
            }
            CP_COMMIT();
        }
        const __half* Ab = Asb[kt & 1];
        const __half* Bb = Bsb[kt & 1];

        #pragma unroll
        for (int kk = 0; kk < 2; kk++) {
            uint32_t af[2][4], bf[4][2];
            #pragma unroll
            for (int mf = 0; mf < 2; mf++) {
                int r0 = 32*wr + 16*mf;
                af[mf][0] = h2bits(*(const __half2*)(Ab + (r0+g  )*AST + 16*kk + 2*q));
                af[mf][1] = h2bits(*(const __half2*)(Ab + (r0+8+g)*AST + 16*kk + 2*q));
                af[mf][2] = h2bits(*(const __half2*)(Ab + (r0+g  )*AST + 16*kk + 8 + 2*q));
                af[mf][3] = h2bits(*(const __half2*)(Ab + (r0+8+g)*AST + 16*kk + 8 + 2*q));
            }
            #pragma unroll
            for (int nf = 0; nf < 4; nf++) {
                int col = 32*wc + 8*nf + g;
                bf[nf][0] = h2bits(*(const __half2*)(Bb + col*BST + 16*kk + 2*q));
                bf[nf][1] = h2bits(*(const __half2*)(Bb + col*BST + 16*kk + 8 + 2*q));
            }
            #pragma unroll
            for (int mf = 0; mf < 2; mf++)
                #pragma unroll
                for (int nf = 0; nf < 4; nf++)
                    mma16(cacc[mf][nf], af[mf], bf[nf][0], bf[nf][1]);
        }
    }

    #pragma unroll
    for (int mf = 0; mf < 2; mf++) {
        #pragma unroll
        for (int rr = 0; rr < 2; rr++) {
            int row = m0 + 32*wr + 16*mf + 8*rr + g;
            #pragma unroll
            for (int nf = 0; nf < 4; nf++) {
                int col = n0 + 32*wc + 8*nf + 2*q;
                float o0 = cacc[mf][nf][rr*2]   + __ldg(bias + col);
                float o1 = cacc[mf][nf][rr*2+1] + __ldg(bias + col + 1);
                if (mode == 0) {
                    __half2 h = __floats2half2_rn(o0*QSCALE, o1*QSCALE);
                    *(uint32_t*)(g_qh + (size_t)row*HID + col) = h2bits(h);
                } else if (mode == 1) {
                    __half2 h = __floats2half2_rn(o0, o1);
                    *(uint32_t*)(g_kh + (size_t)row*HID + col) = h2bits(h);
                } else if (mode == 2) {
                    int hh = col >> 6, dd = col & 63;
                    int s = row & 511, bb = row >> 9;
                    __half* dst = g_vt + (size_t)bb*HD*NKEY + s*16 + hh;
                    dst[(size_t)dd*NKEY]     = __float2half_rn(o0);
                    dst[(size_t)(dd+1)*NKEY] = __float2half_rn(o1);
                } else {
                    *(float2*)(outf + (size_t)row*HID + col) = make_float2(o0, o1);
                }
            }
        }
    }
}

__global__ __launch_bounds__(256)
void qkv_kernel(const float* __restrict__ bq, const float* __restrict__ bk,
                const float* __restrict__ bv)
{
    int z = blockIdx.z;
    const float* bias = (z == 0) ? bq : (z == 1) ? bk : bv;
    gemm_fp16_body(g_xh, g_wh + (size_t)z*HID*HID, bias, z, nullptr);
}

__global__ __launch_bounds__(256)
void oproj_kernel(const float* __restrict__ bo, float* __restrict__ out)
{
    gemm_fp16_body(g_att, g_wh + (size_t)3*HID*HID, bo, 3, out);
}

// ---------------------------------------------------------------------------
// fp16 mma flash attention, key-split 4 ways (R8 inner structure).
// 1024 CTAs = part(4) x B(2) x H(16) x Qtiles(8x64rows), 256 thr = 8 warps.
// Warp: rg=w&3 (16 rows), kh=w>>2 (32-key half). LDSM feed, Q in registers.
// lsum via P @ ones. fp32 partials to gmem; combine kernel normalizes.
// ---------------------------------------------------------------------------
#define KSTH 72
#define KBUF (64*KSTH)
#define OSM_ST 66
#define ATTN_SMEM (4*KBUF*2 + 1024)

__global__ __launch_bounds__(256)
void attn_kernel()
{
    extern __shared__ __align__(16) char smc[];
    __half* sh = (__half*)smc;
    const uint32_t sb = smem_u32(sh);
    const uint32_t ku[2] = { sb, sb + KBUF*2u };
    const uint32_t vu[2] = { sb + 2u*KBUF*2u, sb + 3u*KBUF*2u };
    float* lsumS = (float*)(smc + 4*KBUF*2);
    float* Osm   = (float*)smc;

    const int tid = threadIdx.x;
    const int w = tid >> 5, lane = tid & 31;
    const int g = lane >> 2, q = lane & 3;
    const int lr = lane & 7, lm = lane >> 3;
    const int rg = w & 3, kh = w >> 2;
    const int bx = blockIdx.x;
    const int p  = bx >> 8;
    const int b  = (bx >> 7) & 1;
    const int h  = (bx >> 3) & 15;
    const int s0 = (bx & 7) << 6;

    const __half* kb0 = g_kh + (size_t)b*SEQ*HID;     // [8192][64]
    const __half* vt0 = g_vt + (size_t)b*HD*NKEY;     // [64][8192]
    const int jt0 = p*NTP;

    // prefetch coords: 512 16B-chunks per tile (8 per 64-half row), 2 per thread
    const int pr0 = tid >> 3, pc0 = (tid & 7) << 3;   // rows 0..31
    const int pr1 = pr0 + 32, pc1 = pc0;              // rows 32..63

    {
        const __half* kp = kb0 + (size_t)jt0*64*HD;
        const __half* vp = vt0 + jt0*64;
        cp16(ku[0] + (pr0*KSTH + pc0)*2u, kp + (size_t)pr0*HD + pc0);
        cp16(ku[0] + (pr1*KSTH + pc1)*2u, kp + (size_t)pr1*HD + pc1);
        cp16(vu[0] + (pr0*KSTH + pc0)*2u, vp + (size_t)pr0*NKEY + pc0);
        cp16(vu[0] + (pr1*KSTH + pc1)*2u, vp + (size_t)pr1*NKEY + pc1);
        CP_COMMIT();
    }

    // Q fragments from gmem (pre-scaled fp16)
    uint32_t qf[4][4];
    {
        const __half* qb = g_qh + (size_t)(b*SEQ + s0)*HID + h*HD;
        const __half* q0 = qb + (size_t)(16*rg + g)*HID;
        const __half* q1 = qb + (size_t)(16*rg + 8 + g)*HID;
        #pragma unroll
        for (int kt = 0; kt < 4; kt++) {
            qf[kt][0] = h2bits(*(const __half2*)(q0 + 16*kt + 2*q));
            qf[kt][1] = h2bits(*(const __half2*)(q1 + 16*kt + 2*q));
            qf[kt][2] = h2bits(*(const __half2*)(q0 + 16*kt + 8 + 2*q));
            qf[kt][3] = h2bits(*(const __half2*)(q1 + 16*kt + 8 + 2*q));
        }
    }

    // per-lane LDSM base offsets (bytes)
    const uint32_t koff = (uint32_t)(((32*kh + lr)*KSTH + 16*(lm >> 1) + 8*(lm & 1))*2);
    const uint32_t voff = (uint32_t)(((8*(lm >> 1) + lr)*KSTH + 32*kh + 8*(lm & 1))*2);

    float Oacc[8][4];
    #pragma unroll
    for (int nt = 0; nt < 8; nt++)
        #pragma unroll
        for (int j = 0; j < 4; j++) Oacc[nt][j] = 0.f;
    float lacc[4] = {0.f, 0.f, 0.f, 0.f};

    for (int t = 0; t < NTP; t++) {
        CP_WAIT0();
        __syncthreads();
        if (t + 1 < NTP) {
            int nb = (t+1) & 1;
            const __half* kp = kb0 + (size_t)(jt0+t+1)*64*HD;
            const __half* vp = vt0 + (jt0+t+1)*64;
            cp16(ku[nb] + (pr0*KSTH + pc0)*2u, kp + (size_t)pr0*HD + pc0);
            cp16(ku[nb] + (pr1*KSTH + pc1)*2u, kp + (size_t)pr1*HD + pc1);
            cp16(vu[nb] + (pr0*KSTH + pc0)*2u, vp + (size_t)pr0*NKEY + pc0);
            cp16(vu[nb] + (pr1*KSTH + pc1)*2u, vp + (size_t)pr1*NKEY + pc1);
            CP_COMMIT();
        }
        const uint32_t kcur = ku[t & 1] + koff;
        const uint32_t vcur = vu[t & 1] + voff;

        // ---- S = Q @ K^T : 16 rows x 32 keys ----
        float pch[4][4];
        #pragma unroll
        for (int c = 0; c < 4; c++)
            #pragma unroll
            for (int j = 0; j < 4; j++) pch[c][j] = 0.f;

        #pragma unroll
        for (int c = 0; c < 4; c++) {
            uint32_t kf[8];
            ldsm4(kf,     kcur + (uint32_t)(c*8*KSTH*2));
            ldsm4(kf + 4, kcur + (uint32_t)(c*8*KSTH*2 + 64));
            #pragma unroll
            for (int kt = 0; kt < 4; kt++)
                mma16(pch[c], qf[kt], kf[2*kt], kf[2*kt+1]);
        }

        // ---- per 16-key group: softmax pack, then PV + lsum (tensor pipe) ----
        #pragma unroll
        for (int u = 0; u < 2; u++) {
            uint32_t pa[4];
            pa[0] = h2bits(__floats2half2_rn(ex2(pch[2*u][0]),   ex2(pch[2*u][1])));
            pa[1] = h2bits(__floats2half2_rn(ex2(pch[2*u][2]),   ex2(pch[2*u][3])));
            pa[2] = h2bits(__floats2half2_rn(ex2(pch[2*u+1][0]), ex2(pch[2*u+1][1])));
            pa[3] = h2bits(__floats2half2_rn(ex2(pch[2*u+1][2]), ex2(pch[2*u+1][3])));
            #pragma unroll
            for (int np = 0; np < 4; np++) {
                uint32_t vf[4];
                ldsm4(vf, vcur + (uint32_t)((np*16*KSTH + u*16)*2));
                mma16(Oacc[2*np],     pa, vf[0], vf[1]);
                mma16(Oacc[2*np + 1], pa, vf[2], vf[3]);
            }
            mma16(lacc, pa, ONES2, ONES2);   // exact row sums of rounded P
        }
    }

    // ---- combine kh halves within CTA; write fp32 partials ----
    __syncthreads();   // all K/V reads done before Osm reuse
    if (q == 0) {
        lsumS[kh*64 + 16*rg + g]     = lacc[0];
        lsumS[kh*64 + 16*rg + 8 + g] = lacc[2];
    }
    if (kh == 0) {
        #pragma unroll
        for (int nt = 0; nt < 8; nt++) {
            *(float2*)(Osm + (16*rg + g    )*OSM_ST + 8*nt + 2*q) =
                make_float2(Oacc[nt][0], Oacc[nt][1]);
            *(float2*)(Osm + (16*rg + 8 + g)*OSM_ST + 8*nt + 2*q) =
                make_float2(Oacc[nt][2], Oacc[nt][3]);
        }
    }
    __syncthreads();

    if (kh == 1) {
        int row0 = 16*rg + g, row1 = row0 + 8;
        float l0 = lsumS[row0] + lsumS[64 + row0];
        float l1 = lsumS[row1] + lsumS[64 + row1];
        float* pab = g_po + (size_t)p*ROWS*HID + (size_t)b*SEQ*HID;
        int sA = s0 + row0, sB = s0 + row1;
        if (q == 0) {
            g_pl[((p*BATCH + b)*NH + h)*SEQ + sA] = l0;
            g_pl[((p*BATCH + b)*NH + h)*SEQ + sB] = l1;
        }
        #pragma unroll
        for (int nt = 0; nt < 8; nt++) {
            float2 h0 = *(float2*)(Osm + row0*OSM_ST + 8*nt + 2*q);
            float2 h1 = *(float2*)(Osm + row1*OSM_ST + 8*nt + 2*q);
            int e = h*HD + 8*nt + 2*q;
            size_t base = (size_t)(e >> 1)*HID;
            pab[base + sA]       = Oacc[nt][0] + h0.x;
            pab[base + SEQ + sA] = Oacc[nt][1] + h0.y;
            pab[base + sB]       = Oacc[nt][2] + h1.x;
            pab[base + sB + SEQ] = Oacc[nt][3] + h1.y;
        }
    }
}

// ---------------------------------------------------------------------------
// Combine: g_att = sum_p(po) / sum_p(pl), fp16. 1024 blocks x 256 thr, 4/thr.
// ---------------------------------------------------------------------------
__global__ __launch_bounds__(256)
void combine_kernel()
{
    int i = (blockIdx.x*256 + threadIdx.x)*4;     // half index, 4 per thread
    int b = i >> 19;                              // SEQ*HID = 2^19
    int j = i & (SEQ*HID - 1);
    int r = j >> 10, c = j & 1023;
    int h = r >> 5, s = c & 511;

    float4 asum = *(const float4*)(g_po + i);
    float4 lsum;
    {
        const float* pl = g_pl + (b*NH + h)*SEQ + s;
        lsum = *(const float4*)pl;
        #pragma unroll
        for (int pp = 1; pp < NPART; pp++) {
            float4 a = *(const float4*)(g_po + (size_t)pp*ROWS*HID + i);
            float4 l = *(const float4*)(pl + pp*BATCH*NH*SEQ);
            asum.x += a.x; asum.y += a.y; asum.z += a.z; asum.w += a.w;
            lsum.x += l.x; lsum.y += l.y; lsum.z += l.z; lsum.w += l.w;
        }
    }

    __half2 o01 = __floats2half2_rn(asum.x / lsum.x, asum.y / lsum.y);
    __half2 o23 = __floats2half2_rn(asum.z / lsum.z, asum.w / lsum.w);
    *(uint2*)(g_att + i) = make_uint2(h2bits(o01), h2bits(o23));
}

// ---------------------------------------------------------------------------
extern "C" void kernel_launch(void* const* d_in, const int* in_sizes, int n_in,
                              void* d_out, int out_size)
{
    const float* x  = (const float*)d_in[0];
    const float* Wq = (const float*)d_in[1];
    const float* bq = (const float*)d_in[2];
    const float* Wk = (const float*)d_in[3];
    const float* bk = (const float*)d_in[4];
    const float* Wv = (const float*)d_in[5];
    const float* bv = (const float*)d_in[6];
    const float* Wo = (const float*)d_in[7];
    const float* bo = (const float*)d_in[8];
    float* out = (float*)d_out;

    cudaFuncSetAttribute(qkv_kernel,
                         cudaFuncAttributeMaxDynamicSharedMemorySize, GEMM_SMEM);
    cudaFuncSetAttribute(oproj_kernel,
                         cudaFuncAttributeMaxDynamicSharedMemorySize, GEMM_SMEM);
    cudaFuncSetAttribute(attn_kernel,
                         cudaFuncAttributeMaxDynamicSharedMemorySize, ATTN_SMEM);

    round_x_kernel<<<1024, 256>>>(x);
    transw_kernel<<<dim3(16,16,4), 256>>>(Wq, Wk, Wv, Wo);

    qkv_kernel<<<dim3(8,16,3), 256, GEMM_SMEM>>>(bq, bk, bv);

    attn_kernel<<<NPART*256, 256, ATTN_SMEM>>>();
    combine_kernel<<<ROWS*HID/1024, 256>>>();

    oproj_kernel<<<dim3(8,16), 256, GEMM_SMEM>>>(bo, out);
}